// round 14
// baseline (speedup 1.0000x reference)
#include <cuda_runtime.h>
#include <cuda_fp16.h>
#include <cstdint>

#define N_NODES  100000
#define N_EDGES  1600000
#define N_GRAPHS 1000
#define D        128
#define NOUT     6
#define TILE_M   64
#define NT       1563
#define NT_H0    782
#define HALF_N   50048
#define NB_SCAN  ((N_NODES + 1023) / 1024)   // 98

// ---------------- scratch ------------------------------------------------------
__device__ __align__(16) __half g_fA[N_NODES * D];
__device__ __align__(16) __half g_fB[N_NODES * D];
__device__ int   g_rowptr[N_NODES + 1];
__device__ int   g_pos[N_NODES];
__device__ int   g_col[N_EDGES];
__device__ unsigned long long g_scanpub[NB_SCAN];
__device__ __align__(16) float g_pooled[N_GRAPHS * D];
__device__ int   g_cnt[N_GRAPHS];
__device__ int   g_flag;
__device__ __align__(16) __half g_W[4 * D * D];   // [k][n] fp16

__device__ __forceinline__ long long ld_idx(const void* p, long long i, int wide) {
    return wide ? ((const long long*)p)[i] : (long long)((const int*)p)[i];
}

__global__ void k_zero1(const void* ei) {
    int i = blockIdx.x * blockDim.x + threadIdx.x;
    if (blockIdx.x == 0 && threadIdx.x == 0) {
        const int* p = (const int*)ei;
        int wide = 1;
        for (int k = 0; k < 64; k++)
            if (p[2 * k + 1] != 0) { wide = 0; break; }
        g_flag = wide;
    }
    for (; i < N_NODES + NB_SCAN; i += gridDim.x * blockDim.x) {
        if (i < N_NODES) g_pos[i] = 0;
        else g_scanpub[i - N_NODES] = 0ULL;
    }
}

__global__ void k_zero2() {
    int i = blockIdx.x * blockDim.x + threadIdx.x;
    for (; i < N_GRAPHS * D + N_GRAPHS; i += gridDim.x * blockDim.x) {
        if (i < N_GRAPHS * D) g_pooled[i] = 0.0f;
        else g_cnt[i - N_GRAPHS * D] = 0;
    }
}

// per-graph node counts (off critical path)
__global__ void k_count(const void* batch) {
    int wide = g_flag;
    int n = blockIdx.x * blockDim.x + threadIdx.x;
    for (; n < N_NODES; n += gridDim.x * blockDim.x) {
        int g = (int)ld_idx(batch, n, wide);
        atomicAdd(&g_cnt[g], 1);
    }
}

__global__ void k_wprep(const float* __restrict__ Wa, const float* __restrict__ Wb,
                        const float* __restrict__ Wc, const float* __restrict__ Wd) {
    int idx = blockIdx.x * blockDim.x + threadIdx.x;
    if (idx >= 4 * D * D) return;
    int m = idx >> 14, j = idx & 16383;
    const float* W = (m == 0) ? Wa : (m == 1) ? Wb : (m == 2) ? Wc : Wd;
    g_W[idx] = __float2half_rn(W[j]);
}

// histogram: 2 edges per thread (16B-aligned index loads)
__global__ void k_hist(const void* ei) {
    int wide = g_flag;
    int idx = blockIdx.x * blockDim.x + threadIdx.x;
    long long e = (long long)idx * 2;
    for (; e < N_EDGES; e += (long long)gridDim.x * blockDim.x * 2) {
        int d0, d1;
        if (wide) {
            const uint4 v = *(const uint4*)((const long long*)ei + N_EDGES + e);
            d0 = (int)v.x; d1 = (int)v.z;
        } else {
            const int2 v = *(const int2*)((const int*)ei + N_EDGES + e);
            d0 = v.x; d1 = v.y;
        }
        atomicAdd(&g_pos[d0], 1);
        atomicAdd(&g_pos[d1], 1);
    }
}

// single-kernel scan (decoupled aggregate lookback)
__global__ void k_scanlb() {
    __shared__ int s[1024];
    __shared__ int r[1024];
    int t = threadIdx.x, bid = blockIdx.x;
    int i = bid * 1024 + t;
    int v = (i < N_NODES) ? g_pos[i] : 0;
    s[t] = v;
    __syncthreads();
    for (int off = 1; off < 1024; off <<= 1) {
        int x = (t >= off) ? s[t - off] : 0;
        __syncthreads();
        s[t] += x;
        __syncthreads();
    }
    if (t == 1023)
        atomicExch(&g_scanpub[bid], 0x8000000000000000ULL | (unsigned long long)(unsigned)s[1023]);
    int myagg = 0;
    if (t < bid) {
        unsigned long long pv;
        do { pv = atomicAdd(&g_scanpub[t], 0ULL); } while (pv == 0ULL);
        myagg = (int)(pv & 0xffffffffu);
    }
    r[t] = myagg;
    __syncthreads();
    for (int off = 512; off > 0; off >>= 1) {
        if (t < off) r[t] += r[t + off];
        __syncthreads();
    }
    int off = r[0];
    if (i < N_NODES) {
        int inc = s[t] + off;
        g_rowptr[i + 1] = inc;
        g_pos[i] = inc - v;
    }
    if (i == 0) g_rowptr[0] = 0;
}

// fill: 2 edges per thread
__global__ void k_fill(const void* ei) {
    int wide = g_flag;
    int idx = blockIdx.x * blockDim.x + threadIdx.x;
    long long e = (long long)idx * 2;
    for (; e < N_EDGES; e += (long long)gridDim.x * blockDim.x * 2) {
        int s0, s1, d0, d1;
        if (wide) {
            const uint4 sv = *(const uint4*)((const long long*)ei + e);
            const uint4 dv = *(const uint4*)((const long long*)ei + N_EDGES + e);
            s0 = (int)sv.x; s1 = (int)sv.z;
            d0 = (int)dv.x; d1 = (int)dv.z;
        } else {
            const int2 sv = *(const int2*)((const int*)ei + e);
            const int2 dv = *(const int2*)((const int*)ei + N_EDGES + e);
            s0 = sv.x; s1 = sv.y;
            d0 = dv.x; d1 = dv.y;
        }
        int p0 = atomicAdd(&g_pos[d0], 1);
        g_col[p0] = s0;
        int p1 = atomicAdd(&g_pos[d1], 1);
        g_col[p1] = s1;
    }
}

// ---------------- GEMM infra ---------------------------------------------------
#define LDB    136
#define A_SZ   8704

__device__ __forceinline__ uint32_t smem_u32(const void* p) {
    uint32_t a;
    asm("{ .reg .u64 t; cvta.to.shared.u64 t, %1; cvt.u32.u64 %0, t; }" : "=r"(a) : "l"(p));
    return a;
}
__device__ __forceinline__ void ldsm4(uint32_t& r0, uint32_t& r1, uint32_t& r2, uint32_t& r3, uint32_t addr) {
    asm volatile("ldmatrix.sync.aligned.m8n8.x4.shared.b16 {%0,%1,%2,%3}, [%4];"
                 : "=r"(r0), "=r"(r1), "=r"(r2), "=r"(r3) : "r"(addr));
}
__device__ __forceinline__ void ldsm4t(uint32_t& r0, uint32_t& r1, uint32_t& r2, uint32_t& r3, uint32_t addr) {
    asm volatile("ldmatrix.sync.aligned.m8n8.x4.trans.shared.b16 {%0,%1,%2,%3}, [%4];"
                 : "=r"(r0), "=r"(r1), "=r"(r2), "=r"(r3) : "r"(addr));
}
__device__ __forceinline__ void mma_f16(float* c, uint32_t a0, uint32_t a1, uint32_t a2, uint32_t a3,
                                        uint32_t b0, uint32_t b1) {
    asm volatile("mma.sync.aligned.m16n8k16.row.col.f32.f16.f16.f32 "
                 "{%0,%1,%2,%3}, {%4,%5,%6,%7}, {%8,%9}, {%0,%1,%2,%3};"
                 : "+f"(c[0]), "+f"(c[1]), "+f"(c[2]), "+f"(c[3])
                 : "r"(a0), "r"(a1), "r"(a2), "r"(a3), "r"(b0), "r"(b1));
}
__device__ __forceinline__ void cpa16(uint32_t dst, const void* src, int srcsize) {
    asm volatile("cp.async.cg.shared.global [%0], [%1], 16, %2;"
                 :: "r"(dst), "l"(src), "r"(srcsize));
}

__device__ __forceinline__ void stageA16(uint32_t sb, int base, int tile,
                                         const __half* __restrict__ Ain, int t) {
    const long long blockRow = (long long)tile * TILE_M;
#pragma unroll
    for (int i = 0; i < 4; i++) {
        int lin = t + i * 256;
        int row = lin >> 4, c = (lin & 15) * 8;
        long long gr = blockRow + row;
        int ok = (gr < N_NODES) ? 16 : 0;
        long long src = (gr < N_NODES) ? gr : 0;
        cpa16(sb + 2u * (base + row * LDB + c), Ain + src * 128 + c, ok);
    }
}

#define SMEM_G ((17408 + 2 * A_SZ) * 2)  // 69632

// mode: poolOut -> accumulate into g_pooled (no tensor output); else fp16 out to Ch
__global__ __launch_bounds__(256, 3)
void k_gemm(const __half* __restrict__ Ain, const float* __restrict__ Af32,
            const __half* __restrict__ W, const float* __restrict__ bias,
            __half* __restrict__ Ch, const void* __restrict__ batch,
            int doRelu, int inF32, int tpc, int tileBeg, int tileEnd, int poolOut) {
    extern __shared__ __half sm[];
    __shared__ float sacc[8 * 128];
    __shared__ int sgbase, sgmax;
    const int t = threadIdx.x;
    uint32_t sb = smem_u32(sm);
    const int SM_A0 = 17408;
    const int wide = g_flag;

#pragma unroll
    for (int i = 0; i < 8; i++) {
        int lin = t + i * 256;
        int row = lin >> 4, c = (lin & 15) * 8;
        cpa16(sb + 2u * (row * LDB + c), W + row * 128 + c, 16);
    }
    int tile0 = tileBeg + blockIdx.x * tpc;
    if (tile0 >= tileEnd) return;
    if (inF32) {
        const long long blockRow = (long long)tile0 * TILE_M;
#pragma unroll
        for (int i = 0; i < 4; i++) {
            int lin = t + i * 256;
            int row = lin >> 4, c = (lin & 15) * 8;
            long long gr = blockRow + row;
            float4 v0 = make_float4(0.f, 0.f, 0.f, 0.f), v1 = v0;
            if (gr < N_NODES) {
                v0 = *(const float4*)&Af32[gr * 128 + c];
                v1 = *(const float4*)&Af32[gr * 128 + c + 4];
            }
            __half2 h0 = __floats2half2_rn(v0.x, v0.y);
            __half2 h1 = __floats2half2_rn(v0.z, v0.w);
            __half2 h2 = __floats2half2_rn(v1.x, v1.y);
            __half2 h3 = __floats2half2_rn(v1.z, v1.w);
            *(uint4*)&sm[SM_A0 + row * LDB + c] =
                make_uint4(*(unsigned*)&h0, *(unsigned*)&h1, *(unsigned*)&h2, *(unsigned*)&h3);
        }
    } else {
        stageA16(sb, SM_A0, tile0, Ain, t);
    }
    asm volatile("cp.async.commit_group;" ::: "memory");

    const int w = t >> 5, lane = t & 31;
    const int mbase = (w >> 1) * 16;
    const int nbase = (w & 1) * 64;
    const int lrow = lane & 15;
    const int lcol = (lane >> 4) * 8;
    const int colb = nbase + 2 * (lane & 3);

    float bx[8], by[8];
#pragma unroll
    for (int nf = 0; nf < 8; nf++) {
        bx[nf] = 0.f; by[nf] = 0.f;
        if (bias) { float2 bb = *(const float2*)&bias[colb + nf * 8]; bx[nf] = bb.x; by[nf] = bb.y; }
    }

    int buf = 0;
    for (int it = 0; it < tpc; it++) {
        int tile = tile0 + it;
        if (tile >= tileEnd) break;
        int havenext = (it + 1 < tpc) && (tile + 1 < tileEnd) && !inF32;
        if (havenext) stageA16(sb, SM_A0 + (buf ^ 1) * A_SZ, tile + 1, Ain, t);
        asm volatile("cp.async.commit_group;" ::: "memory");
        if (havenext) asm volatile("cp.async.wait_group 1;" ::: "memory");
        else          asm volatile("cp.async.wait_group 0;" ::: "memory");

        if (poolOut) {
            // zero per-tile pool buffer
            for (int i = t; i < 8 * 128; i += 256) sacc[i] = 0.f;
            if (t == 0) {
                sgbase = (int)ld_idx(batch, (long long)tile * TILE_M, wide);
                sgmax = 0;
            }
        }
        __syncthreads();

        float acc[8][4];
#pragma unroll
        for (int nf = 0; nf < 8; nf++)
#pragma unroll
            for (int r = 0; r < 4; r++) acc[nf][r] = 0.f;

        const int aBase = 17408 + buf * A_SZ;
#pragma unroll
        for (int kk = 0; kk < 8; kk++) {
            const int k0 = kk * 16;
            uint32_t a0, a1, a2, a3;
            ldsm4(a0, a1, a2, a3, sb + 2u * (aBase + (mbase + lrow) * LDB + k0 + lcol));
            uint32_t b[4][4];
#pragma unroll
            for (int ni = 0; ni < 4; ni++)
                ldsm4t(b[ni][0], b[ni][1], b[ni][2], b[ni][3],
                       sb + 2u * ((k0 + lrow) * LDB + nbase + ni * 16 + lcol));
#pragma unroll
            for (int ni = 0; ni < 4; ni++) {
                mma_f16(acc[2 * ni],     a0, a1, a2, a3, b[ni][0], b[ni][1]);
                mma_f16(acc[2 * ni + 1], a0, a1, a2, a3, b[ni][2], b[ni][3]);
            }
        }

        const long long r0 = (long long)tile * TILE_M + mbase + (lane >> 2);
        if (poolOut) {
            int gbase = sgbase;
#pragma unroll
            for (int half = 0; half < 2; half++) {
                long long rr = r0 + half * 8;
                if (rr >= N_NODES) continue;
                int grel = (int)ld_idx(batch, rr, wide) - gbase;
#pragma unroll
                for (int nf = 0; nf < 8; nf++) {
                    float vx = acc[nf][half * 2 + 0] + bx[nf];
                    float vy = acc[nf][half * 2 + 1] + by[nf];
                    if (grel < 8) {
                        atomicAdd(&sacc[grel * 128 + colb + nf * 8], vx);
                        atomicAdd(&sacc[grel * 128 + colb + nf * 8 + 1], vy);
                    } else {
                        atomicAdd(&g_pooled[(gbase + grel) * D + colb + nf * 8], vx);
                        atomicAdd(&g_pooled[(gbase + grel) * D + colb + nf * 8 + 1], vy);
                    }
                }
                if ((lane & 3) == 0 && grel < 8) atomicMax(&sgmax, grel);
            }
            __syncthreads();
            int gm = sgmax;
            for (int i = t; i < (gm + 1) * 128; i += 256)
                atomicAdd(&g_pooled[(sgbase + (i >> 7)) * D + (i & 127)], sacc[i]);
        } else {
#pragma unroll
            for (int nf = 0; nf < 8; nf++) {
#pragma unroll
                for (int half = 0; half < 2; half++) {
                    long long rr = r0 + half * 8;
                    if (rr >= N_NODES) continue;
                    float vx = acc[nf][half * 2 + 0] + bx[nf];
                    float vy = acc[nf][half * 2 + 1] + by[nf];
                    if (doRelu) { vx = fmaxf(vx, 0.f); vy = fmaxf(vy, 0.f); }
                    __half2 h = __floats2half2_rn(vx, vy);
                    *(unsigned*)&Ch[rr * 128 + colb + nf * 8] = *(unsigned*)&h;
                }
            }
        }
        __syncthreads();
        buf ^= 1;
    }
}

// ---------- fused double GEMM --------------------------------------------------
#define SMEM_G2 ((2 * 17408 + 2 * A_SZ) * 2)   // 104448

__global__ __launch_bounds__(256, 2)
void k_gemm2x(const __half* __restrict__ Ain,
              const __half* __restrict__ W1, const __half* __restrict__ W2,
              const float* __restrict__ b1, __half* __restrict__ Cout,
              int tpc, int tileBeg, int tileEnd) {
    extern __shared__ __half sm[];
    const int t = threadIdx.x;
    uint32_t sb = smem_u32(sm);
    const int SM_W2 = 17408;
    const int SM_A0 = 2 * 17408;

#pragma unroll
    for (int i = 0; i < 8; i++) {
        int lin = t + i * 256;
        int row = lin >> 4, c = (lin & 15) * 8;
        cpa16(sb + 2u * (row * LDB + c),          W1 + row * 128 + c, 16);
        cpa16(sb + 2u * (SM_W2 + row * LDB + c),  W2 + row * 128 + c, 16);
    }
    int tile0 = tileBeg + blockIdx.x * tpc;
    if (tile0 >= tileEnd) return;
    stageA16(sb, SM_A0, tile0, Ain, t);
    asm volatile("cp.async.commit_group;" ::: "memory");

    const int w = t >> 5, lane = t & 31;
    const int mbase = (w >> 1) * 16;
    const int nbase = (w & 1) * 64;
    const int lrow = lane & 15;
    const int lcol = (lane >> 4) * 8;
    const int colb = nbase + 2 * (lane & 3);

    float bx[8], by[8];
#pragma unroll
    for (int nf = 0; nf < 8; nf++) {
        float2 bb = *(const float2*)&b1[colb + nf * 8];
        bx[nf] = bb.x; by[nf] = bb.y;
    }

    int buf = 0;
    for (int it = 0; it < tpc; it++) {
        int tile = tile0 + it;
        if (tile >= tileEnd) break;
        int havenext = (it + 1 < tpc) && (tile + 1 < tileEnd);
        if (havenext) stageA16(sb, SM_A0 + (buf ^ 1) * A_SZ, tile + 1, Ain, t);
        asm volatile("cp.async.commit_group;" ::: "memory");
        if (havenext) asm volatile("cp.async.wait_group 1;" ::: "memory");
        else          asm volatile("cp.async.wait_group 0;" ::: "memory");
        __syncthreads();

        const int aBase = SM_A0 + buf * A_SZ;
        float acc[8][4];

#pragma unroll
        for (int nf = 0; nf < 8; nf++)
#pragma unroll
            for (int r = 0; r < 4; r++) acc[nf][r] = 0.f;
#pragma unroll
        for (int kk = 0; kk < 8; kk++) {
            const int k0 = kk * 16;
            uint32_t a0, a1, a2, a3;
            ldsm4(a0, a1, a2, a3, sb + 2u * (aBase + (mbase + lrow) * LDB + k0 + lcol));
            uint32_t b[4][4];
#pragma unroll
            for (int ni = 0; ni < 4; ni++)
                ldsm4t(b[ni][0], b[ni][1], b[ni][2], b[ni][3],
                       sb + 2u * ((k0 + lrow) * LDB + nbase + ni * 16 + lcol));
#pragma unroll
            for (int ni = 0; ni < 4; ni++) {
                mma_f16(acc[2 * ni],     a0, a1, a2, a3, b[ni][0], b[ni][1]);
                mma_f16(acc[2 * ni + 1], a0, a1, a2, a3, b[ni][2], b[ni][3]);
            }
        }
        __syncthreads();

#pragma unroll
        for (int nf = 0; nf < 8; nf++) {
#pragma unroll
            for (int half = 0; half < 2; half++) {
                int row = mbase + (lane >> 2) + half * 8;
                float vx = fmaxf(acc[nf][half * 2 + 0] + bx[nf], 0.f);
                float vy = fmaxf(acc[nf][half * 2 + 1] + by[nf], 0.f);
                __half2 h = __floats2half2_rn(vx, vy);
                *(unsigned*)&sm[aBase + row * LDB + colb + nf * 8] = *(unsigned*)&h;
            }
        }
        __syncthreads();

#pragma unroll
        for (int nf = 0; nf < 8; nf++)
#pragma unroll
            for (int r = 0; r < 4; r++) acc[nf][r] = 0.f;
#pragma unroll
        for (int kk = 0; kk < 8; kk++) {
            const int k0 = kk * 16;
            uint32_t a0, a1, a2, a3;
            ldsm4(a0, a1, a2, a3, sb + 2u * (aBase + (mbase + lrow) * LDB + k0 + lcol));
            uint32_t b[4][4];
#pragma unroll
            for (int ni = 0; ni < 4; ni++)
                ldsm4t(b[ni][0], b[ni][1], b[ni][2], b[ni][3],
                       sb + 2u * (SM_W2 + (k0 + lrow) * LDB + nbase + ni * 16 + lcol));
#pragma unroll
            for (int ni = 0; ni < 4; ni++) {
                mma_f16(acc[2 * ni],     a0, a1, a2, a3, b[ni][0], b[ni][1]);
                mma_f16(acc[2 * ni + 1], a0, a1, a2, a3, b[ni][2], b[ni][3]);
            }
        }

        const long long r0 = (long long)tile * TILE_M + mbase + (lane >> 2);
#pragma unroll
        for (int nf = 0; nf < 8; nf++) {
#pragma unroll
            for (int half = 0; half < 2; half++) {
                long long rr = r0 + half * 8;
                if (rr >= N_NODES) continue;
                __half2 h = __floats2half2_rn(acc[nf][half * 2 + 0], acc[nf][half * 2 + 1]);
                *(unsigned*)&Cout[rr * 128 + colb + nf * 8] = *(unsigned*)&h;
            }
        }
        __syncthreads();
        buf ^= 1;
    }
}

// agg + bias + relu: 2 nodes per warp, uint4 lanes
__device__ __forceinline__ void addrow(float* a, uint4 v) {
    __half2* hp = (__half2*)&v;
#pragma unroll
    for (int q = 0; q < 4; q++) {
        float2 f = __half22float2(hp[q]);
        a[2 * q] += f.x; a[2 * q + 1] += f.y;
    }
}

__global__ void k_aggbr(const __half* __restrict__ in, __half* __restrict__ out,
                        const float* __restrict__ bias, int nodeBeg, int nodeEnd) {
    int gwarp = (blockIdx.x * blockDim.x + threadIdx.x) >> 5;
    int halfid = (threadIdx.x >> 4) & 1;
    int l16 = threadIdx.x & 15;
    int node = nodeBeg + gwarp * 2 + halfid;
    if (node >= nodeEnd) return;
    const uint4* in4 = (const uint4*)in;
    float a[8];
    {
        uint4 sv = in4[(long long)node * 16 + l16];
        __half2* hp = (__half2*)&sv;
#pragma unroll
        for (int q = 0; q < 4; q++) {
            float2 f = __half22float2(hp[q]);
            a[2 * q] = f.x; a[2 * q + 1] = f.y;
        }
    }
    int j = g_rowptr[node], end = g_rowptr[node + 1];
    for (; j + 4 <= end; j += 4) {
        int c0 = g_col[j], c1 = g_col[j + 1], c2 = g_col[j + 2], c3 = g_col[j + 3];
        uint4 v0 = in4[(long long)c0 * 16 + l16];
        uint4 v1 = in4[(long long)c1 * 16 + l16];
        uint4 v2 = in4[(long long)c2 * 16 + l16];
        uint4 v3 = in4[(long long)c3 * 16 + l16];
        addrow(a, v0); addrow(a, v1); addrow(a, v2); addrow(a, v3);
    }
    for (; j < end; j++) {
        uint4 v = in4[(long long)g_col[j] * 16 + l16];
        addrow(a, v);
    }
    float4 b0 = *(const float4*)&bias[l16 * 8];
    float4 b1 = *(const float4*)&bias[l16 * 8 + 4];
    a[0] = fmaxf(a[0] + b0.x, 0.f); a[1] = fmaxf(a[1] + b0.y, 0.f);
    a[2] = fmaxf(a[2] + b0.z, 0.f); a[3] = fmaxf(a[3] + b0.w, 0.f);
    a[4] = fmaxf(a[4] + b1.x, 0.f); a[5] = fmaxf(a[5] + b1.y, 0.f);
    a[6] = fmaxf(a[6] + b1.z, 0.f); a[7] = fmaxf(a[7] + b1.w, 0.f);
    __half2 h0 = __floats2half2_rn(a[0], a[1]);
    __half2 h1 = __floats2half2_rn(a[2], a[3]);
    __half2 h2 = __floats2half2_rn(a[4], a[5]);
    __half2 h3 = __floats2half2_rn(a[6], a[7]);
    ((uint4*)out)[(long long)node * 16 + l16] =
        make_uint4(*(unsigned*)&h0, *(unsigned*)&h1, *(unsigned*)&h2, *(unsigned*)&h3);
}

__global__ void k_final(const float* __restrict__ Wlin, const float* __restrict__ blin,
                        float* __restrict__ out) {
    int g = blockIdx.x;
    int k = threadIdx.x;
    float c = (float)g_cnt[g];
    if (c < 1.0f) c = 1.0f;
    float v = g_pooled[g * D + k] / c;
    __shared__ float red[128];
    for (int j = 0; j < NOUT; j++) {
        red[k] = v * Wlin[k * NOUT + j];
        __syncthreads();
        for (int s = 64; s > 0; s >>= 1) {
            if (k < s) red[k] += red[k + s];
            __syncthreads();
        }
        if (k == 0) out[g * NOUT + j] = red[0] + blin[j];
        __syncthreads();
    }
}

// ---------------- launch ------------------------------------------------------
extern "C" void kernel_launch(void* const* d_in, const int* in_sizes, int n_in,
                              void* d_out, int out_size) {
    const float* x    = (const float*)d_in[0];
    const void*  ei   = d_in[1];
    const void*  batch= d_in[2];
    const float* b1a  = (const float*)d_in[4];
    const float* b1b  = (const float*)d_in[6];
    const float* b2a  = (const float*)d_in[8];
    const float* b2b  = (const float*)d_in[10];
    const float* Wlin = (const float*)d_in[11];
    const float* blin = (const float*)d_in[12];
    float* out = (float*)d_out;

    __half *fA, *fB, *w16;
    cudaGetSymbolAddress((void**)&fA,  g_fA);
    cudaGetSymbolAddress((void**)&fB,  g_fB);
    cudaGetSymbolAddress((void**)&w16, g_W);

    static cudaStream_t s2;
    static cudaEvent_t e1, e2, e3, e6, e7, e8;
    static int inited = 0;
    if (!inited) {
        cudaStreamCreateWithFlags(&s2, cudaStreamNonBlocking);
        cudaEventCreateWithFlags(&e1, cudaEventDisableTiming);
        cudaEventCreateWithFlags(&e2, cudaEventDisableTiming);
        cudaEventCreateWithFlags(&e3, cudaEventDisableTiming);
        cudaEventCreateWithFlags(&e6, cudaEventDisableTiming);
        cudaEventCreateWithFlags(&e7, cudaEventDisableTiming);
        cudaEventCreateWithFlags(&e8, cudaEventDisableTiming);
        cudaFuncSetAttribute(k_gemm,   cudaFuncAttributeMaxDynamicSharedMemorySize, SMEM_G);
        cudaFuncSetAttribute(k_gemm2x, cudaFuncAttributeMaxDynamicSharedMemorySize, SMEM_G2);
        inited = 1;
    }

    const int aggB0 = ((HALF_N + 1) / 2 * 32 + 255) / 256;
    const int aggB1 = (((N_NODES - HALF_N) + 1) / 2 * 32 + 255) / 256;
    const int g2x0 = (NT_H0 + 3) / 4;
    const int g2x1 = (NT - NT_H0 + 3) / 4;

    k_zero1<<<200, 512>>>(ei);
    cudaEventRecord(e1, 0);

    // s0: wprep -> zero2 -> count -> gemm1
    k_wprep<<<(4 * D * D + 255) / 256, 256>>>((const float*)d_in[3], (const float*)d_in[5],
                                              (const float*)d_in[7], (const float*)d_in[9]);
    k_zero2<<<127, 512>>>();
    k_count<<<392, 256>>>(batch);
    // s2: CSR chain
    cudaStreamWaitEvent(s2, e1, 0);
    k_hist<<<3125, 256, 0, s2>>>(ei);
    k_gemm<<<NT, 256, SMEM_G>>>(nullptr, x, w16, nullptr, fB, nullptr, 0, 1, 1, 0, NT, 0);  // u
    cudaEventRecord(e3, 0);
    k_scanlb<<<NB_SCAN, 1024, 0, s2>>>();
    k_fill<<<3125, 256, 0, s2>>>(ei);
    cudaEventRecord(e2, s2);

    // agg1 halves
    cudaStreamWaitEvent(0, e2, 0);
    cudaStreamWaitEvent(s2, e3, 0);
    k_aggbr<<<aggB0, 256>>>(fB, fA, b1a, 0, HALF_N);
    k_aggbr<<<aggB1, 256, 0, s2>>>(fB, fA, b1a, HALF_N, N_NODES);

    // fused gemm2+3 halves
    k_gemm2x<<<g2x0, 256, SMEM_G2>>>(fA, w16 + D * D, w16 + 2 * D * D, b1b, fB, 4, 0, NT_H0);
    cudaEventRecord(e7, 0);
    k_gemm2x<<<g2x1, 256, SMEM_G2, s2>>>(fA, w16 + D * D, w16 + 2 * D * D, b1b, fB, 4, NT_H0, NT);
    cudaEventRecord(e6, s2);

    // agg2 halves
    cudaStreamWaitEvent(0, e6, 0);
    cudaStreamWaitEvent(s2, e7, 0);
    k_aggbr<<<aggB0, 256>>>(fB, fA, b2a, 0, HALF_N);
    k_aggbr<<<aggB1, 256, 0, s2>>>(fB, fA, b2a, HALF_N, N_NODES);

    // gemm4 halves with fused pooling (r = q@W2b + b2b accumulated per graph)
    k_gemm<<<g2x0, 256, SMEM_G>>>(fA, nullptr, w16 + 3 * D * D, b2b, fB, batch, 0, 0, 4, 0, NT_H0, 1);
    k_gemm<<<g2x1, 256, SMEM_G, s2>>>(fA, nullptr, w16 + 3 * D * D, b2b, fB, batch, 0, 0, 4, NT_H0, NT, 1);
    cudaEventRecord(e8, s2);
    cudaStreamWaitEvent(0, e8, 0);
    k_final<<<N_GRAPHS, 128>>>(Wlin, blin, out);
}

// round 15
// speedup vs baseline: 1.2138x; 1.2138x over previous
#include <cuda_runtime.h>
#include <cuda_fp16.h>
#include <cstdint>

#define N_NODES  100000
#define N_EDGES  1600000
#define N_GRAPHS 1000
#define D        128
#define NOUT     6
#define TILE_M   64
#define NT       1563
#define NT_H0    782
#define HALF_N   50048
#define NB_SCAN  ((N_NODES + 1023) / 1024)   // 98

// ---------------- scratch ------------------------------------------------------
__device__ __align__(16) __half g_fA[N_NODES * D];
__device__ __align__(16) __half g_fB[N_NODES * D];
__device__ int   g_rowptr[N_NODES + 1];
__device__ int   g_pos[N_NODES];
__device__ int   g_col[N_EDGES];
__device__ unsigned long long g_scanpub[NB_SCAN];
__device__ __align__(16) float g_pooled[N_GRAPHS * D];
__device__ int   g_cnt[N_GRAPHS];
__device__ int   g_flag;
__device__ __align__(16) __half g_W[4 * D * D];   // [k][n] fp16

__device__ __forceinline__ long long ld_idx(const void* p, long long i, int wide) {
    return wide ? ((const long long*)p)[i] : (long long)((const int*)p)[i];
}

// zero CSR-critical state + dtype detect
__global__ void k_zero1(const void* ei) {
    int i = blockIdx.x * blockDim.x + threadIdx.x;
    if (blockIdx.x == 0 && threadIdx.x == 0) {
        const int* p = (const int*)ei;
        int wide = 1;
        for (int k = 0; k < 64; k++)
            if (p[2 * k + 1] != 0) { wide = 0; break; }
        g_flag = wide;
    }
    for (; i < N_NODES + NB_SCAN; i += gridDim.x * blockDim.x) {
        if (i < N_NODES) g_pos[i] = 0;
        else g_scanpub[i - N_NODES] = 0ULL;
    }
}

// zero pool state (off critical path)
__global__ void k_zero2() {
    int i = blockIdx.x * blockDim.x + threadIdx.x;
    for (; i < N_GRAPHS * D + N_GRAPHS; i += gridDim.x * blockDim.x) {
        if (i < N_GRAPHS * D) g_pooled[i] = 0.0f;
        else g_cnt[i - N_GRAPHS * D] = 0;
    }
}

__global__ void k_wprep(const float* __restrict__ Wa, const float* __restrict__ Wb,
                        const float* __restrict__ Wc, const float* __restrict__ Wd) {
    int idx = blockIdx.x * blockDim.x + threadIdx.x;
    if (idx >= 4 * D * D) return;
    int m = idx >> 14, j = idx & 16383;
    const float* W = (m == 0) ? Wa : (m == 1) ? Wb : (m == 2) ? Wc : Wd;
    g_W[idx] = __float2half_rn(W[j]);
}

// histogram: 2 edges per thread (paired index loads)
__global__ void k_hist(const void* ei) {
    int wide = g_flag;
    int idx = blockIdx.x * blockDim.x + threadIdx.x;
    long long e = (long long)idx * 2;
    for (; e < N_EDGES; e += (long long)gridDim.x * blockDim.x * 2) {
        int d0, d1;
        if (wide) {
            const uint4 v = *(const uint4*)((const long long*)ei + N_EDGES + e);
            d0 = (int)v.x; d1 = (int)v.z;
        } else {
            const int2 v = *(const int2*)((const int*)ei + N_EDGES + e);
            d0 = v.x; d1 = v.y;
        }
        atomicAdd(&g_pos[d0], 1);
        atomicAdd(&g_pos[d1], 1);
    }
}

// single-kernel scan (decoupled aggregate lookback; 98 blocks, all resident)
__global__ void k_scanlb() {
    __shared__ int s[1024];
    __shared__ int r[1024];
    int t = threadIdx.x, bid = blockIdx.x;
    int i = bid * 1024 + t;
    int v = (i < N_NODES) ? g_pos[i] : 0;
    s[t] = v;
    __syncthreads();
    for (int off = 1; off < 1024; off <<= 1) {
        int x = (t >= off) ? s[t - off] : 0;
        __syncthreads();
        s[t] += x;
        __syncthreads();
    }
    if (t == 1023)
        atomicExch(&g_scanpub[bid], 0x8000000000000000ULL | (unsigned long long)(unsigned)s[1023]);
    int myagg = 0;
    if (t < bid) {
        unsigned long long pv;
        do { pv = atomicAdd(&g_scanpub[t], 0ULL); } while (pv == 0ULL);
        myagg = (int)(pv & 0xffffffffu);
    }
    r[t] = myagg;
    __syncthreads();
    for (int off = 512; off > 0; off >>= 1) {
        if (t < off) r[t] += r[t + off];
        __syncthreads();
    }
    int off = r[0];
    if (i < N_NODES) {
        int inc = s[t] + off;
        g_rowptr[i + 1] = inc;
        g_pos[i] = inc - v;
    }
    if (i == 0) g_rowptr[0] = 0;
}

// fill: 2 edges per thread (paired index loads)
__global__ void k_fill(const void* ei) {
    int wide = g_flag;
    int idx = blockIdx.x * blockDim.x + threadIdx.x;
    long long e = (long long)idx * 2;
    for (; e < N_EDGES; e += (long long)gridDim.x * blockDim.x * 2) {
        int s0, s1, d0, d1;
        if (wide) {
            const uint4 sv = *(const uint4*)((const long long*)ei + e);
            const uint4 dv = *(const uint4*)((const long long*)ei + N_EDGES + e);
            s0 = (int)sv.x; s1 = (int)sv.z;
            d0 = (int)dv.x; d1 = (int)dv.z;
        } else {
            const int2 sv = *(const int2*)((const int*)ei + e);
            const int2 dv = *(const int2*)((const int*)ei + N_EDGES + e);
            s0 = sv.x; s1 = sv.y;
            d0 = dv.x; d1 = dv.y;
        }
        int p0 = atomicAdd(&g_pos[d0], 1);
        g_col[p0] = s0;
        int p1 = atomicAdd(&g_pos[d1], 1);
        g_col[p1] = s1;
    }
}

// ---------------- GEMM infra ---------------------------------------------------
#define LDB    136
#define A_SZ   8704

__device__ __forceinline__ uint32_t smem_u32(const void* p) {
    uint32_t a;
    asm("{ .reg .u64 t; cvta.to.shared.u64 t, %1; cvt.u32.u64 %0, t; }" : "=r"(a) : "l"(p));
    return a;
}
__device__ __forceinline__ void ldsm4(uint32_t& r0, uint32_t& r1, uint32_t& r2, uint32_t& r3, uint32_t addr) {
    asm volatile("ldmatrix.sync.aligned.m8n8.x4.shared.b16 {%0,%1,%2,%3}, [%4];"
                 : "=r"(r0), "=r"(r1), "=r"(r2), "=r"(r3) : "r"(addr));
}
__device__ __forceinline__ void ldsm4t(uint32_t& r0, uint32_t& r1, uint32_t& r2, uint32_t& r3, uint32_t addr) {
    asm volatile("ldmatrix.sync.aligned.m8n8.x4.trans.shared.b16 {%0,%1,%2,%3}, [%4];"
                 : "=r"(r0), "=r"(r1), "=r"(r2), "=r"(r3) : "r"(addr));
}
__device__ __forceinline__ void mma_f16(float* c, uint32_t a0, uint32_t a1, uint32_t a2, uint32_t a3,
                                        uint32_t b0, uint32_t b1) {
    asm volatile("mma.sync.aligned.m16n8k16.row.col.f32.f16.f16.f32 "
                 "{%0,%1,%2,%3}, {%4,%5,%6,%7}, {%8,%9}, {%0,%1,%2,%3};"
                 : "+f"(c[0]), "+f"(c[1]), "+f"(c[2]), "+f"(c[3])
                 : "r"(a0), "r"(a1), "r"(a2), "r"(a3), "r"(b0), "r"(b1));
}
__device__ __forceinline__ void cpa16(uint32_t dst, const void* src, int srcsize) {
    asm volatile("cp.async.cg.shared.global [%0], [%1], 16, %2;"
                 :: "r"(dst), "l"(src), "r"(srcsize));
}

__device__ __forceinline__ void stageA16(uint32_t sb, int base, int tile,
                                         const __half* __restrict__ Ain, int t) {
    const long long blockRow = (long long)tile * TILE_M;
#pragma unroll
    for (int i = 0; i < 4; i++) {
        int lin = t + i * 256;
        int row = lin >> 4, c = (lin & 15) * 8;
        long long gr = blockRow + row;
        int ok = (gr < N_NODES) ? 16 : 0;
        long long src = (gr < N_NODES) ? gr : 0;
        cpa16(sb + 2u * (base + row * LDB + c), Ain + src * 128 + c, ok);
    }
}

#define SMEM_G ((17408 + 2 * A_SZ) * 2)  // 69632

__global__ __launch_bounds__(256, 3)
void k_gemm(const __half* __restrict__ Ain, const float* __restrict__ Af32,
            const __half* __restrict__ W, const float* __restrict__ bias,
            __half* __restrict__ Ch,
            int doRelu, int inF32, int tpc, int tileBeg, int tileEnd) {
    extern __shared__ __half sm[];
    const int t = threadIdx.x;
    uint32_t sb = smem_u32(sm);
    const int SM_A0 = 17408;

#pragma unroll
    for (int i = 0; i < 8; i++) {
        int lin = t + i * 256;
        int row = lin >> 4, c = (lin & 15) * 8;
        cpa16(sb + 2u * (row * LDB + c), W + row * 128 + c, 16);
    }
    int tile0 = tileBeg + blockIdx.x * tpc;
    if (tile0 >= tileEnd) return;
    if (inF32) {
        const long long blockRow = (long long)tile0 * TILE_M;
#pragma unroll
        for (int i = 0; i < 4; i++) {
            int lin = t + i * 256;
            int row = lin >> 4, c = (lin & 15) * 8;
            long long gr = blockRow + row;
            float4 v0 = make_float4(0.f, 0.f, 0.f, 0.f), v1 = v0;
            if (gr < N_NODES) {
                v0 = *(const float4*)&Af32[gr * 128 + c];
                v1 = *(const float4*)&Af32[gr * 128 + c + 4];
            }
            __half2 h0 = __floats2half2_rn(v0.x, v0.y);
            __half2 h1 = __floats2half2_rn(v0.z, v0.w);
            __half2 h2 = __floats2half2_rn(v1.x, v1.y);
            __half2 h3 = __floats2half2_rn(v1.z, v1.w);
            *(uint4*)&sm[SM_A0 + row * LDB + c] =
                make_uint4(*(unsigned*)&h0, *(unsigned*)&h1, *(unsigned*)&h2, *(unsigned*)&h3);
        }
    } else {
        stageA16(sb, SM_A0, tile0, Ain, t);
    }
    asm volatile("cp.async.commit_group;" ::: "memory");

    const int w = t >> 5, lane = t & 31;
    const int mbase = (w >> 1) * 16;
    const int nbase = (w & 1) * 64;
    const int lrow = lane & 15;
    const int lcol = (lane >> 4) * 8;
    const int colb = nbase + 2 * (lane & 3);

    float bx[8], by[8];
#pragma unroll
    for (int nf = 0; nf < 8; nf++) {
        bx[nf] = 0.f; by[nf] = 0.f;
        if (bias) { float2 bb = *(const float2*)&bias[colb + nf * 8]; bx[nf] = bb.x; by[nf] = bb.y; }
    }

    int buf = 0;
    for (int it = 0; it < tpc; it++) {
        int tile = tile0 + it;
        if (tile >= tileEnd) break;
        int havenext = (it + 1 < tpc) && (tile + 1 < tileEnd) && !inF32;
        if (havenext) stageA16(sb, SM_A0 + (buf ^ 1) * A_SZ, tile + 1, Ain, t);
        asm volatile("cp.async.commit_group;" ::: "memory");
        if (havenext) asm volatile("cp.async.wait_group 1;" ::: "memory");
        else          asm volatile("cp.async.wait_group 0;" ::: "memory");
        __syncthreads();

        float acc[8][4];
#pragma unroll
        for (int nf = 0; nf < 8; nf++)
#pragma unroll
            for (int r = 0; r < 4; r++) acc[nf][r] = 0.f;

        const int aBase = 17408 + buf * A_SZ;
#pragma unroll
        for (int kk = 0; kk < 8; kk++) {
            const int k0 = kk * 16;
            uint32_t a0, a1, a2, a3;
            ldsm4(a0, a1, a2, a3, sb + 2u * (aBase + (mbase + lrow) * LDB + k0 + lcol));
            uint32_t b[4][4];
#pragma unroll
            for (int ni = 0; ni < 4; ni++)
                ldsm4t(b[ni][0], b[ni][1], b[ni][2], b[ni][3],
                       sb + 2u * ((k0 + lrow) * LDB + nbase + ni * 16 + lcol));
#pragma unroll
            for (int ni = 0; ni < 4; ni++) {
                mma_f16(acc[2 * ni],     a0, a1, a2, a3, b[ni][0], b[ni][1]);
                mma_f16(acc[2 * ni + 1], a0, a1, a2, a3, b[ni][2], b[ni][3]);
            }
        }

        const long long r0 = (long long)tile * TILE_M + mbase + (lane >> 2);
#pragma unroll
        for (int nf = 0; nf < 8; nf++) {
#pragma unroll
            for (int half = 0; half < 2; half++) {
                long long rr = r0 + half * 8;
                if (rr >= N_NODES) continue;
                float vx = acc[nf][half * 2 + 0] + bx[nf];
                float vy = acc[nf][half * 2 + 1] + by[nf];
                if (doRelu) { vx = fmaxf(vx, 0.f); vy = fmaxf(vy, 0.f); }
                __half2 h = __floats2half2_rn(vx, vy);
                *(unsigned*)&Ch[rr * 128 + colb + nf * 8] = *(unsigned*)&h;
            }
        }
        __syncthreads();
        buf ^= 1;
    }
}

// ---------- fused double GEMM --------------------------------------------------
#define SMEM_G2 ((2 * 17408 + 2 * A_SZ) * 2)   // 104448

__global__ __launch_bounds__(256, 2)
void k_gemm2x(const __half* __restrict__ Ain,
              const __half* __restrict__ W1, const __half* __restrict__ W2,
              const float* __restrict__ b1, __half* __restrict__ Cout,
              int tpc, int tileBeg, int tileEnd) {
    extern __shared__ __half sm[];
    const int t = threadIdx.x;
    uint32_t sb = smem_u32(sm);
    const int SM_W2 = 17408;
    const int SM_A0 = 2 * 17408;

#pragma unroll
    for (int i = 0; i < 8; i++) {
        int lin = t + i * 256;
        int row = lin >> 4, c = (lin & 15) * 8;
        cpa16(sb + 2u * (row * LDB + c),          W1 + row * 128 + c, 16);
        cpa16(sb + 2u * (SM_W2 + row * LDB + c),  W2 + row * 128 + c, 16);
    }
    int tile0 = tileBeg + blockIdx.x * tpc;
    if (tile0 >= tileEnd) return;
    stageA16(sb, SM_A0, tile0, Ain, t);
    asm volatile("cp.async.commit_group;" ::: "memory");

    const int w = t >> 5, lane = t & 31;
    const int mbase = (w >> 1) * 16;
    const int nbase = (w & 1) * 64;
    const int lrow = lane & 15;
    const int lcol = (lane >> 4) * 8;
    const int colb = nbase + 2 * (lane & 3);

    float bx[8], by[8];
#pragma unroll
    for (int nf = 0; nf < 8; nf++) {
        float2 bb = *(const float2*)&b1[colb + nf * 8];
        bx[nf] = bb.x; by[nf] = bb.y;
    }

    int buf = 0;
    for (int it = 0; it < tpc; it++) {
        int tile = tile0 + it;
        if (tile >= tileEnd) break;
        int havenext = (it + 1 < tpc) && (tile + 1 < tileEnd);
        if (havenext) stageA16(sb, SM_A0 + (buf ^ 1) * A_SZ, tile + 1, Ain, t);
        asm volatile("cp.async.commit_group;" ::: "memory");
        if (havenext) asm volatile("cp.async.wait_group 1;" ::: "memory");
        else          asm volatile("cp.async.wait_group 0;" ::: "memory");
        __syncthreads();

        const int aBase = SM_A0 + buf * A_SZ;
        float acc[8][4];

        // pass 1: h = relu(v@W1 + b1)
#pragma unroll
        for (int nf = 0; nf < 8; nf++)
#pragma unroll
            for (int r = 0; r < 4; r++) acc[nf][r] = 0.f;
#pragma unroll
        for (int kk = 0; kk < 8; kk++) {
            const int k0 = kk * 16;
            uint32_t a0, a1, a2, a3;
            ldsm4(a0, a1, a2, a3, sb + 2u * (aBase + (mbase + lrow) * LDB + k0 + lcol));
            uint32_t b[4][4];
#pragma unroll
            for (int ni = 0; ni < 4; ni++)
                ldsm4t(b[ni][0], b[ni][1], b[ni][2], b[ni][3],
                       sb + 2u * ((k0 + lrow) * LDB + nbase + ni * 16 + lcol));
#pragma unroll
            for (int ni = 0; ni < 4; ni++) {
                mma_f16(acc[2 * ni],     a0, a1, a2, a3, b[ni][0], b[ni][1]);
                mma_f16(acc[2 * ni + 1], a0, a1, a2, a3, b[ni][2], b[ni][3]);
            }
        }
        __syncthreads();

#pragma unroll
        for (int nf = 0; nf < 8; nf++) {
#pragma unroll
            for (int half = 0; half < 2; half++) {
                int row = mbase + (lane >> 2) + half * 8;
                float vx = fmaxf(acc[nf][half * 2 + 0] + bx[nf], 0.f);
                float vy = fmaxf(acc[nf][half * 2 + 1] + by[nf], 0.f);
                __half2 h = __floats2half2_rn(vx, vy);
                *(unsigned*)&sm[aBase + row * LDB + colb + nf * 8] = *(unsigned*)&h;
            }
        }
        __syncthreads();

        // pass 2: p = h@W2
#pragma unroll
        for (int nf = 0; nf < 8; nf++)
#pragma unroll
            for (int r = 0; r < 4; r++) acc[nf][r] = 0.f;
#pragma unroll
        for (int kk = 0; kk < 8; kk++) {
            const int k0 = kk * 16;
            uint32_t a0, a1, a2, a3;
            ldsm4(a0, a1, a2, a3, sb + 2u * (aBase + (mbase + lrow) * LDB + k0 + lcol));
            uint32_t b[4][4];
#pragma unroll
            for (int ni = 0; ni < 4; ni++)
                ldsm4t(b[ni][0], b[ni][1], b[ni][2], b[ni][3],
                       sb + 2u * (SM_W2 + (k0 + lrow) * LDB + nbase + ni * 16 + lcol));
#pragma unroll
            for (int ni = 0; ni < 4; ni++) {
                mma_f16(acc[2 * ni],     a0, a1, a2, a3, b[ni][0], b[ni][1]);
                mma_f16(acc[2 * ni + 1], a0, a1, a2, a3, b[ni][2], b[ni][3]);
            }
        }

        const long long r0 = (long long)tile * TILE_M + mbase + (lane >> 2);
#pragma unroll
        for (int nf = 0; nf < 8; nf++) {
#pragma unroll
            for (int half = 0; half < 2; half++) {
                long long rr = r0 + half * 8;
                if (rr >= N_NODES) continue;
                __half2 h = __floats2half2_rn(acc[nf][half * 2 + 0], acc[nf][half * 2 + 1]);
                *(unsigned*)&Cout[rr * 128 + colb + nf * 8] = *(unsigned*)&h;
            }
        }
        __syncthreads();
        buf ^= 1;
    }
}

// agg + bias + relu: 2 nodes per warp, uint4 lanes
__device__ __forceinline__ void addrow(float* a, uint4 v) {
    __half2* hp = (__half2*)&v;
#pragma unroll
    for (int q = 0; q < 4; q++) {
        float2 f = __half22float2(hp[q]);
        a[2 * q] += f.x; a[2 * q + 1] += f.y;
    }
}

__global__ void k_aggbr(const __half* __restrict__ in, __half* __restrict__ out,
                        const float* __restrict__ bias, int nodeBeg, int nodeEnd) {
    int gwarp = (blockIdx.x * blockDim.x + threadIdx.x) >> 5;
    int halfid = (threadIdx.x >> 4) & 1;
    int l16 = threadIdx.x & 15;
    int node = nodeBeg + gwarp * 2 + halfid;
    if (node >= nodeEnd) return;
    const uint4* in4 = (const uint4*)in;
    float a[8];
    {
        uint4 sv = in4[(long long)node * 16 + l16];
        __half2* hp = (__half2*)&sv;
#pragma unroll
        for (int q = 0; q < 4; q++) {
            float2 f = __half22float2(hp[q]);
            a[2 * q] = f.x; a[2 * q + 1] = f.y;
        }
    }
    int j = g_rowptr[node], end = g_rowptr[node + 1];
    for (; j + 4 <= end; j += 4) {
        int c0 = g_col[j], c1 = g_col[j + 1], c2 = g_col[j + 2], c3 = g_col[j + 3];
        uint4 v0 = in4[(long long)c0 * 16 + l16];
        uint4 v1 = in4[(long long)c1 * 16 + l16];
        uint4 v2 = in4[(long long)c2 * 16 + l16];
        uint4 v3 = in4[(long long)c3 * 16 + l16];
        addrow(a, v0); addrow(a, v1); addrow(a, v2); addrow(a, v3);
    }
    for (; j < end; j++) {
        uint4 v = in4[(long long)g_col[j] * 16 + l16];
        addrow(a, v);
    }
    float4 b0 = *(const float4*)&bias[l16 * 8];
    float4 b1 = *(const float4*)&bias[l16 * 8 + 4];
    a[0] = fmaxf(a[0] + b0.x, 0.f); a[1] = fmaxf(a[1] + b0.y, 0.f);
    a[2] = fmaxf(a[2] + b0.z, 0.f); a[3] = fmaxf(a[3] + b0.w, 0.f);
    a[4] = fmaxf(a[4] + b1.x, 0.f); a[5] = fmaxf(a[5] + b1.y, 0.f);
    a[6] = fmaxf(a[6] + b1.z, 0.f); a[7] = fmaxf(a[7] + b1.w, 0.f);
    __half2 h0 = __floats2half2_rn(a[0], a[1]);
    __half2 h1 = __floats2half2_rn(a[2], a[3]);
    __half2 h2 = __floats2half2_rn(a[4], a[5]);
    __half2 h3 = __floats2half2_rn(a[6], a[7]);
    ((uint4*)out)[(long long)node * 16 + l16] =
        make_uint4(*(unsigned*)&h0, *(unsigned*)&h1, *(unsigned*)&h2, *(unsigned*)&h3);
}

// pool over node range (+ per-graph counts fused)
#define NODES_PER_BLK 128
__global__ void k_pool(const __half* __restrict__ h, const void* batch,
                       int nodeBeg, int nodeEnd) {
    int wide = g_flag;
    int f = threadIdx.x;
    int base = nodeBeg + blockIdx.x * NODES_PER_BLK;
    int end = base + NODES_PER_BLK;
    if (end > nodeEnd) end = nodeEnd;
    if (base >= nodeEnd) return;
    float run = 0.0f;
    int cur = -1, nrun = 0;
    for (int n = base; n < end; n++) {
        int g = (int)ld_idx(batch, n, wide);
        if (g != cur) {
            if (cur >= 0) {
                atomicAdd(&g_pooled[cur * D + f], run);
                if (f == 0) atomicAdd(&g_cnt[cur], nrun);
            }
            cur = g; run = 0.0f; nrun = 0;
        }
        run += __half2float(h[(long long)n * D + f]);
        nrun++;
    }
    if (cur >= 0) {
        atomicAdd(&g_pooled[cur * D + f], run);
        if (f == 0) atomicAdd(&g_cnt[cur], nrun);
    }
}

__global__ void k_final(const float* __restrict__ Wlin, const float* __restrict__ blin,
                        float* __restrict__ out) {
    int g = blockIdx.x;
    int k = threadIdx.x;
    float c = (float)g_cnt[g];
    if (c < 1.0f) c = 1.0f;
    float v = g_pooled[g * D + k] / c;
    __shared__ float red[128];
    for (int j = 0; j < NOUT; j++) {
        red[k] = v * Wlin[k * NOUT + j];
        __syncthreads();
        for (int s = 64; s > 0; s >>= 1) {
            if (k < s) red[k] += red[k + s];
            __syncthreads();
        }
        if (k == 0) out[g * NOUT + j] = red[0] + blin[j];
        __syncthreads();
    }
}

// ---------------- launch ------------------------------------------------------
extern "C" void kernel_launch(void* const* d_in, const int* in_sizes, int n_in,
                              void* d_out, int out_size) {
    const float* x    = (const float*)d_in[0];
    const void*  ei   = d_in[1];
    const void*  batch= d_in[2];
    const float* b1a  = (const float*)d_in[4];
    const float* b1b  = (const float*)d_in[6];
    const float* b2a  = (const float*)d_in[8];
    const float* b2b  = (const float*)d_in[10];
    const float* Wlin = (const float*)d_in[11];
    const float* blin = (const float*)d_in[12];
    float* out = (float*)d_out;

    __half *fA, *fB, *w16;
    cudaGetSymbolAddress((void**)&fA,  g_fA);
    cudaGetSymbolAddress((void**)&fB,  g_fB);
    cudaGetSymbolAddress((void**)&w16, g_W);

    static cudaStream_t s2;
    static cudaEvent_t e1, e2, e3, e6, e7, e8;
    static int inited = 0;
    if (!inited) {
        cudaStreamCreateWithFlags(&s2, cudaStreamNonBlocking);
        cudaEventCreateWithFlags(&e1, cudaEventDisableTiming);
        cudaEventCreateWithFlags(&e2, cudaEventDisableTiming);
        cudaEventCreateWithFlags(&e3, cudaEventDisableTiming);
        cudaEventCreateWithFlags(&e6, cudaEventDisableTiming);
        cudaEventCreateWithFlags(&e7, cudaEventDisableTiming);
        cudaEventCreateWithFlags(&e8, cudaEventDisableTiming);
        cudaFuncSetAttribute(k_gemm,   cudaFuncAttributeMaxDynamicSharedMemorySize, SMEM_G);
        cudaFuncSetAttribute(k_gemm2x, cudaFuncAttributeMaxDynamicSharedMemorySize, SMEM_G2);
        inited = 1;
    }

    const int aggB0 = ((HALF_N + 1) / 2 * 32 + 255) / 256;
    const int aggB1 = (((N_NODES - HALF_N) + 1) / 2 * 32 + 255) / 256;
    const int poolB0 = (HALF_N + NODES_PER_BLK - 1) / NODES_PER_BLK;
    const int poolB1 = (N_NODES - HALF_N + NODES_PER_BLK - 1) / NODES_PER_BLK;
    const int g2x0 = (NT_H0 + 3) / 4;
    const int g2x1 = (NT - NT_H0 + 3) / 4;

    k_zero1<<<200, 512>>>(ei);
    cudaEventRecord(e1, 0);

    // s0: wprep -> gemm1 -> zero2 (zero2 only needed before pool)
    k_wprep<<<(4 * D * D + 255) / 256, 256>>>((const float*)d_in[3], (const float*)d_in[5],
                                              (const float*)d_in[7], (const float*)d_in[9]);
    // s2: CSR chain (forked after zero1)
    cudaStreamWaitEvent(s2, e1, 0);
    k_hist<<<3125, 256, 0, s2>>>(ei);
    k_gemm<<<NT, 256, SMEM_G>>>(nullptr, x, w16, nullptr, fB, 0, 1, 1, 0, NT);  // u
    cudaEventRecord(e3, 0);
    k_zero2<<<127, 512>>>();
    k_scanlb<<<NB_SCAN, 1024, 0, s2>>>();
    k_fill<<<3125, 256, 0, s2>>>(ei);
    cudaEventRecord(e2, s2);

    // agg1 halves
    cudaStreamWaitEvent(0, e2, 0);
    cudaStreamWaitEvent(s2, e3, 0);
    k_aggbr<<<aggB0, 256>>>(fB, fA, b1a, 0, HALF_N);
    k_aggbr<<<aggB1, 256, 0, s2>>>(fB, fA, b1a, HALF_N, N_NODES);

    // fused gemm2+3 halves
    k_gemm2x<<<g2x0, 256, SMEM_G2>>>(fA, w16 + D * D, w16 + 2 * D * D, b1b, fB, 4, 0, NT_H0);
    cudaEventRecord(e7, 0);
    k_gemm2x<<<g2x1, 256, SMEM_G2, s2>>>(fA, w16 + D * D, w16 + 2 * D * D, b1b, fB, 4, NT_H0, NT);
    cudaEventRecord(e6, s2);

    // agg2 halves
    cudaStreamWaitEvent(0, e6, 0);
    cudaStreamWaitEvent(s2, e7, 0);
    k_aggbr<<<aggB0, 256>>>(fB, fA, b2a, 0, HALF_N);
    k_aggbr<<<aggB1, 256, 0, s2>>>(fB, fA, b2a, HALF_N, N_NODES);

    // gemm4 halves + pool halves
    k_gemm<<<g2x0, 256, SMEM_G>>>(fA, nullptr, w16 + 3 * D * D, b2b, fB, 0, 0, 4, 0, NT_H0);
    k_gemm<<<g2x1, 256, SMEM_G, s2>>>(fA, nullptr, w16 + 3 * D * D, b2b, fB, 0, 0, 4, NT_H0, NT);
    k_pool<<<poolB0, 128>>>(fB, batch, 0, HALF_N);
    k_pool<<<poolB1, 128, 0, s2>>>(fB, batch, HALF_N, N_NODES);
    cudaEventRecord(e8, s2);
    cudaStreamWaitEvent(0, e8, 0);
    k_final<<<N_GRAPHS, 128>>>(Wlin, blin, out);
}